// round 9
// baseline (speedup 1.0000x reference)
#include <cuda_runtime.h>
#include <cstdint>
#include <math.h>

// ---------------- problem constants ----------------
#define BATCH   8
#define C2DIM   128
#define C3DIM   256
#define HDIM    28
#define WDIM    28
#define H3      14
#define W3      14
#define CDIM    384
#define NPATCH  6272
#define MBANK   30000
#define MBANK_PAD 30720             // 3 splits * 40 tiles * 256 rows

// ---------------- tiling ----------------
#define MSPLIT   3
#define TILE_M   128                // patches per CTA
#define TILE_N   256                // bank rows per CTA tile
#define NTILES   49                 // NPATCH / TILE_M
#define BTILES   40                 // bank tiles per split (40*256 = 10240)

#define ASTRIDE  400                // bytes per A row in smem (384 + 16 pad)
#define ABYTES   (128 * ASTRIDE)    // 51200
#define BROWB    80                 // bytes per B row (64 s8 + 16 pad)
#define NSTAGE   3
#define PAIRSTG  (32 * BROWB)       // 2560: one pair-stage (32 rows x 64 k-bytes)
#define PAIRB    (NSTAGE * PAIRSTG) // 7680 per pair
#define SM_TOTAL (ABYTES + 8 * PAIRB)   // 112640

#define NTHREADS 512
#define TILEBYTES ((size_t)TILE_N * CDIM)   // gmem bytes per bank tile row-block

// ---------------- scratch ----------------
__device__ __align__(16) int8_t g_pat_s8[(size_t)NPATCH * CDIM];
__device__ __align__(16) int8_t g_bank_s8[(size_t)MBANK_PAD * CDIM];
__device__ float  g_xscale[NPATCH];
__device__ float  g_xsq[NPATCH];
__device__ float2 g_bstat[MBANK_PAD];       // (msq, scale)
__device__ float  g_part[MSPLIT * NPATCH];

__device__ __forceinline__ uint32_t s2u(const void* p) {
    uint32_t r;
    asm("{ .reg .u64 t; cvta.to.shared.u64 t, %1; cvt.u32.u64 %0, t; }"
        : "=r"(r) : "l"(p));
    return r;
}

// ============================ prep kernels ============================
// One warp per patch: embed (f2 concat bilinear-upsampled f3), per-row absmax
// quantize to s8, write q-row + scale + quantized squared norm.
__global__ void embedq_kernel(const float* __restrict__ f2,
                              const float* __restrict__ f3) {
    int n    = (blockIdx.x * blockDim.x + threadIdx.x) >> 5;
    int lane = threadIdx.x & 31;
    if (n >= NPATCH) return;
    int b = n / (HDIM * WDIM);
    int hw = n - b * (HDIM * WDIM);
    int h = hw / WDIM;
    int w = hw - h * WDIM;

    // bilinear coords (same for all c3)
    float sh = h * 0.5f - 0.25f;
    float sw = w * 0.5f - 0.25f;
    int h0 = (int)floorf(sh);
    int w0 = (int)floorf(sw);
    float th = sh - (float)h0;
    float tw = sw - (float)w0;
    int h0c = h0 < 0 ? 0 : h0;   int h1c = h0 + 1 > H3 - 1 ? H3 - 1 : h0 + 1;
    int w0c = w0 < 0 ? 0 : w0;   int w1c = w0 + 1 > W3 - 1 ? W3 - 1 : w0 + 1;

    float vals[12];
    #pragma unroll
    for (int j = 0; j < 12; ++j) {
        int c = lane + j * 32;
        if (c < C2DIM) {
            vals[j] = f2[(((size_t)b * C2DIM + c) * HDIM + h) * WDIM + w];
        } else {
            int c3 = c - C2DIM;
            const float* base = f3 + ((size_t)b * C3DIM + c3) * (H3 * W3);
            float v00 = base[h0c * W3 + w0c];
            float v01 = base[h0c * W3 + w1c];
            float v10 = base[h1c * W3 + w0c];
            float v11 = base[h1c * W3 + w1c];
            vals[j] = (1.f - th) * ((1.f - tw) * v00 + tw * v01)
                    +        th  * ((1.f - tw) * v10 + tw * v11);
        }
    }
    float amax = 0.f;
    #pragma unroll
    for (int j = 0; j < 12; ++j) amax = fmaxf(amax, fabsf(vals[j]));
    #pragma unroll
    for (int off = 16; off; off >>= 1)
        amax = fmaxf(amax, __shfl_xor_sync(0xffffffffu, amax, off));
    float s   = (amax > 0.f) ? amax * (1.f / 127.f) : 1.f;
    float inv = (amax > 0.f) ? 127.f / amax : 0.f;

    float sumsq = 0.f;
    int8_t* dst = g_pat_s8 + (size_t)n * CDIM;
    #pragma unroll
    for (int j = 0; j < 12; ++j) {
        float qf = rintf(vals[j] * inv);
        dst[lane + j * 32] = (int8_t)(int)qf;
        sumsq += qf * qf;
    }
    #pragma unroll
    for (int off = 16; off; off >>= 1)
        sumsq += __shfl_xor_sync(0xffffffffu, sumsq, off);
    if (lane == 0) {
        g_xscale[n] = s;
        g_xsq[n] = s * s * sumsq;
    }
}

// One warp per bank row: quantize + (msq, scale); pad rows -> q=0, msq=inf.
__global__ void bankq_kernel(const float* __restrict__ bank) {
    int row  = (blockIdx.x * blockDim.x + threadIdx.x) >> 5;
    int lane = threadIdx.x & 31;
    if (row >= MBANK_PAD) return;
    int8_t* dst = g_bank_s8 + (size_t)row * CDIM;
    if (row >= MBANK) {
        #pragma unroll
        for (int j = 0; j < 12; ++j) dst[lane + j * 32] = 0;
        if (lane == 0) g_bstat[row] = make_float2(__int_as_float(0x7f800000), 0.f);
        return;
    }
    const float* src = bank + (size_t)row * CDIM;
    float vals[12];
    #pragma unroll
    for (int j = 0; j < 12; ++j) vals[j] = src[lane + j * 32];
    float amax = 0.f;
    #pragma unroll
    for (int j = 0; j < 12; ++j) amax = fmaxf(amax, fabsf(vals[j]));
    #pragma unroll
    for (int off = 16; off; off >>= 1)
        amax = fmaxf(amax, __shfl_xor_sync(0xffffffffu, amax, off));
    float s   = (amax > 0.f) ? amax * (1.f / 127.f) : 1.f;
    float inv = (amax > 0.f) ? 127.f / amax : 0.f;
    float sumsq = 0.f;
    #pragma unroll
    for (int j = 0; j < 12; ++j) {
        float qf = rintf(vals[j] * inv);
        dst[lane + j * 32] = (int8_t)(int)qf;
        sumsq += qf * qf;
    }
    #pragma unroll
    for (int off = 16; off; off >>= 1)
        sumsq += __shfl_xor_sync(0xffffffffu, sumsq, off);
    if (lane == 0) g_bstat[row] = make_float2(s * s * sumsq, s);
}

// ============================ main GEMM+min kernel ============================
// 512 threads, 16 warps in 2(m) x 8(n); warp tile 64x32, mma.m16n8k32 s8.s32.
// Warp-pair (wm0,wm1 of same wn) shares a private 3-stage B ring; pairs sync
// with named bar.sync. j-loop fully unrolled (6 chunks, stage = j%3).
__global__ void __launch_bounds__(NTHREADS, 1) nn_kernel() {
    extern __shared__ __align__(1024) char smem[];
    char* Asm = smem;
    const int tid  = threadIdx.x;
    const int lane = tid & 31;
    const int wid  = tid >> 5;
    const int wm   = wid >> 3;      // 0..1
    const int wn   = wid & 7;       // 0..7
    const int n0   = blockIdx.x * TILE_M;
    const int split = blockIdx.y;
    const int mbase = split * (BTILES * TILE_N);

    const uint32_t aSm = s2u(smem);
    const uint32_t bSm = aSm + ABYTES + (uint32_t)wn * PAIRB;   // pair region

    // ---- load A tile (128 rows x 384 s8) into smem, stride 400 ----
    #pragma unroll
    for (int i = 0; i < 6; ++i) {
        int e = i * NTHREADS + tid;
        int r = e / 24, q = e - r * 24;
        uint4 v = *(const uint4*)(g_pat_s8 + (size_t)(n0 + r) * CDIM + q * 16);
        *(uint4*)(Asm + r * ASTRIDE + q * 16) = v;
    }

    // per-lane ldmatrix base addresses (s8 k32 frag via b16 ldmatrix)
    const uint32_t aBase = aSm + (wm * 64 + (lane & 15)) * ASTRIDE
                         + (lane >> 4) * 16;
    const int lq = lane >> 3;
    const int bn = (lane & 7) + ((lq >> 1) << 3);    // local n-row 0..15
    const int bko = (lq & 1) * 16;                   // k-byte half 0/16
    const uint32_t bBase = bSm + bn * BROWB + bko;

    // per-thread patch scales for my 8 accumulator rows
    float xs[4][2];
    {
        int r0 = n0 + wm * 64 + (lane >> 2);
        #pragma unroll
        for (int mt = 0; mt < 4; ++mt) {
            xs[mt][0] = __ldg(&g_xscale[r0 + mt * 16]);
            xs[mt][1] = __ldg(&g_xscale[r0 + mt * 16 + 8]);
        }
    }

    float rowmin[4][2];
    #pragma unroll
    for (int i = 0; i < 4; ++i) {
        rowmin[i][0] = __int_as_float(0x7f800000);
        rowmin[i][1] = __int_as_float(0x7f800000);
    }

    // ---- pair chunk loader: 32 rows x 64 k-bytes = 2KB, 2 warps split ----
    const int l64 = wm * 32 + lane;   // 0..63 within the pair
    const int lr = l64 >> 2, lqq = l64 & 3;   // rows lr, lr+16; quad lqq
    auto load_at = [&](const char* src0, uint32_t dbase) {
        #pragma unroll
        for (int i = 0; i < 2; ++i) {
            int r = lr + i * 16;
            uint32_t d = dbase + r * BROWB + lqq * 16;
            const char* s = src0 + (size_t)r * CDIM + lqq * 16;
            asm volatile("cp.async.cg.shared.global [%0], [%1], 16;"
                         :: "r"(d), "l"(s));
        }
        asm volatile("cp.async.commit_group;");
    };

    // pair's gmem base for tile 0
    const char* tileSrc = (const char*)(g_bank_s8 +
                          (size_t)(mbase + wn * 32) * CDIM);

    load_at(tileSrc + 0 * 64, bSm + 0 * PAIRSTG);   // chunk 0 -> stage 0
    load_at(tileSrc + 1 * 64, bSm + 1 * PAIRSTG);   // chunk 1 -> stage 1
    __syncthreads();   // covers A-tile stores

    const int barid = wn + 1;
    for (int t = 0; t < BTILES; ++t) {
        int acc[4][4][4];
        #pragma unroll
        for (int mt = 0; mt < 4; ++mt)
            #pragma unroll
            for (int nt = 0; nt < 4; ++nt)
                #pragma unroll
                for (int e = 0; e < 4; ++e) acc[mt][nt][e] = 0;

        const bool more = (t + 1) < BTILES;
        const char* nextSrc = tileSrc + TILEBYTES;
        float2 bs[4][2];

        #pragma unroll
        for (int j = 0; j < 6; ++j) {
            asm volatile("cp.async.wait_group 1;");   // own chunk j resident
            asm volatile("bar.sync %0, 64;" :: "r"(barid) : "memory");
            // load chunk j+2 into stage (j+2)%3
            if (j < 4) {
                load_at(tileSrc + (j + 2) * 64,
                        bSm + (uint32_t)(((j + 2) % 3) * PAIRSTG));
            } else if (more) {
                load_at(nextSrc + (j - 4) * 64,
                        bSm + (uint32_t)(((j + 2) % 3) * PAIRSTG));
            } else {
                asm volatile("cp.async.commit_group;");  // keep group count
            }
            if (j == 5) {   // prefetch bank stats for the fold (hidden by MMAs)
                const int cb = mbase + t * TILE_N + wn * 32 + (lane & 3) * 2;
                #pragma unroll
                for (int nt = 0; nt < 4; ++nt) {
                    bs[nt][0] = __ldg(&g_bstat[cb + nt * 8]);
                    bs[nt][1] = __ldg(&g_bstat[cb + nt * 8 + 1]);
                }
            }

            const uint32_t bBuf = bBase + (uint32_t)((j % 3) * PAIRSTG);
            #pragma unroll
            for (int s = 0; s < 2; ++s) {
                // B frags: 2 x4-ldmatrix -> 4 n8-tiles x {b0,b1}
                uint32_t b[4][2];
                #pragma unroll
                for (int np = 0; np < 2; ++np) {
                    uint32_t r0, r1, r2, r3;
                    uint32_t ad = bBuf + np * (16 * BROWB) + s * 32;
                    asm volatile(
                        "ldmatrix.sync.aligned.m8n8.x4.shared.b16 "
                        "{%0,%1,%2,%3}, [%4];"
                        : "=r"(r0), "=r"(r1), "=r"(r2), "=r"(r3) : "r"(ad));
                    b[2 * np][0] = r0; b[2 * np][1] = r1;
                    b[2 * np + 1][0] = r2; b[2 * np + 1][1] = r3;
                }
                // A frags: 4 x4-ldmatrix -> 4 m16-tiles x {a0..a3}
                uint32_t a[4][4];
                #pragma unroll
                for (int mt = 0; mt < 4; ++mt) {
                    uint32_t ad = aBase + mt * (16 * ASTRIDE)
                                + j * 64 + s * 32;
                    asm volatile(
                        "ldmatrix.sync.aligned.m8n8.x4.shared.b16 "
                        "{%0,%1,%2,%3}, [%4];"
                        : "=r"(a[mt][0]), "=r"(a[mt][1]),
                          "=r"(a[mt][2]), "=r"(a[mt][3]) : "r"(ad));
                }
                #pragma unroll
                for (int mt = 0; mt < 4; ++mt)
                    #pragma unroll
                    for (int nt = 0; nt < 4; ++nt) {
                        asm volatile(
                            "mma.sync.aligned.m16n8k32.row.col.s32.s8.s8.s32 "
                            "{%0,%1,%2,%3}, {%4,%5,%6,%7}, {%8,%9}, {%0,%1,%2,%3};"
                            : "+r"(acc[mt][nt][0]), "+r"(acc[mt][nt][1]),
                              "+r"(acc[mt][nt][2]), "+r"(acc[mt][nt][3])
                            : "r"(a[mt][0]), "r"(a[mt][1]),
                              "r"(a[mt][2]), "r"(a[mt][3]),
                              "r"(b[nt][0]), "r"(b[nt][1]));
                    }
            }
        }
        tileSrc = nextSrc;

        // ---- fold tile into persistent row-min regs ----
        // v = msq_m + (-2 * sx * sm) * dot
        #pragma unroll
        for (int nt = 0; nt < 4; ++nt) {
            float m0 = bs[nt][0].x, w0 = -2.f * bs[nt][0].y;
            float m1 = bs[nt][1].x, w1 = -2.f * bs[nt][1].y;
            #pragma unroll
            for (int mt = 0; mt < 4; ++mt) {
                float f0 = (float)acc[mt][nt][0];
                float f1 = (float)acc[mt][nt][1];
                float f2v = (float)acc[mt][nt][2];
                float f3v = (float)acc[mt][nt][3];
                float v0 = fmaf(xs[mt][0] * w0, f0, m0);
                float v1 = fmaf(xs[mt][0] * w1, f1, m1);
                float v2 = fmaf(xs[mt][1] * w0, f2v, m0);
                float v3 = fmaf(xs[mt][1] * w1, f3v, m1);
                rowmin[mt][0] = fminf(rowmin[mt][0], fminf(v0, v1));
                rowmin[mt][1] = fminf(rowmin[mt][1], fminf(v2, v3));
            }
        }
    }

    // ---- final reduction: lanes sharing rows, then across wn warps ----
    #pragma unroll
    for (int mt = 0; mt < 4; ++mt)
        #pragma unroll
        for (int h = 0; h < 2; ++h) {
            float v = rowmin[mt][h];
            v = fminf(v, __shfl_xor_sync(0xffffffffu, v, 1));
            v = fminf(v, __shfl_xor_sync(0xffffffffu, v, 2));
            rowmin[mt][h] = v;
        }
    asm volatile("cp.async.wait_group 0;");
    __syncthreads();
    float* red = (float*)Asm;      // [8 wn][128 rows], aliases A region
    if ((lane & 3) == 0) {
        #pragma unroll
        for (int mt = 0; mt < 4; ++mt)
            #pragma unroll
            for (int h = 0; h < 2; ++h) {
                int row = wm * 64 + mt * 16 + (lane >> 2) + h * 8;
                red[wn * 128 + row] = rowmin[mt][h];
            }
    }
    __syncthreads();
    if (tid < 128) {
        float v = red[tid];
        #pragma unroll
        for (int wq = 1; wq < 8; ++wq)
            v = fminf(v, red[wq * 128 + tid]);
        g_part[split * NPATCH + n0 + tid] = v;
    }
}

// ============================ finalize ============================
__global__ void finalize_kernel(float* __restrict__ out) {
    int n = blockIdx.x * blockDim.x + threadIdx.x;
    if (n >= NPATCH) return;
    float m = fminf(g_part[n], fminf(g_part[NPATCH + n], g_part[2 * NPATCH + n]));
    float d2 = g_xsq[n] + m;
    d2 = fmaxf(d2, 1e-12f);
    out[n] = sqrtf(d2);
}

__global__ void img_max_kernel(float* __restrict__ out) {
    __shared__ float red[8];
    int b = blockIdx.x;
    int tid = threadIdx.x;
    float v = -3.0e38f;
    for (int i = tid; i < HDIM * WDIM; i += blockDim.x)
        v = fmaxf(v, out[b * (HDIM * WDIM) + i]);
    #pragma unroll
    for (int off = 16; off; off >>= 1)
        v = fmaxf(v, __shfl_xor_sync(0xffffffffu, v, off));
    if ((tid & 31) == 0) red[tid >> 5] = v;
    __syncthreads();
    if (tid < 8) {
        v = red[tid];
        #pragma unroll
        for (int off = 4; off; off >>= 1)
            v = fmaxf(v, __shfl_xor_sync(0x000000ffu, v, off));
        if (tid == 0) out[NPATCH + b] = v;
    }
}

// ============================ launch ============================
extern "C" void kernel_launch(void* const* d_in, const int* in_sizes, int n_in,
                              void* d_out, int out_size) {
    const float* f2   = (const float*)d_in[0];
    const float* f3   = (const float*)d_in[1];
    const float* bank = (const float*)d_in[2];
    float* out = (float*)d_out;

    cudaFuncSetAttribute(nn_kernel,
                         cudaFuncAttributeMaxDynamicSharedMemorySize, SM_TOTAL);

    embedq_kernel<<<(NPATCH * 32 + 255) / 256, 256>>>(f2, f3);
    bankq_kernel<<<(MBANK_PAD * 32 + 255) / 256, 256>>>(bank);

    dim3 grid(NTILES, MSPLIT);
    nn_kernel<<<grid, NTHREADS, SM_TOTAL>>>();

    finalize_kernel<<<(NPATCH + 255) / 256, 256>>>(out);
    if (out_size >= NPATCH + BATCH)
        img_max_kernel<<<BATCH, 256>>>(out);
}

// round 10
// speedup vs baseline: 3.3134x; 3.3134x over previous
#include <cuda_runtime.h>
#include <cuda_bf16.h>
#include <cstdint>

// ---------------- problem constants ----------------
#define BATCH   8
#define C2DIM   128
#define C3DIM   256
#define HDIM    28
#define WDIM    28
#define H3      14
#define W3      14
#define CDIM    384
#define NPATCH  6272
#define MBANK   30000
#define MBANK_PAD 30720             // 3 splits * 40 tiles * 256 rows

// ---------------- tiling ----------------
#define MSPLIT   3
#define TILE_M   128                // patches per CTA
#define TILE_N   256                // bank rows per CTA tile
#define NTILES   49                 // NPATCH / TILE_M
#define BTILES   40                 // bank tiles per split (40*256 = 10240)

#define ASTRIDE  392                // bf16 elems per A row (384 + 8 pad)
#define ABYTES   (128 * ASTRIDE * 2)    // 100352
#define BROWB    144                // bytes per B row (64 bf16 + 8 pad)
#define NSTAGE   3
#define PAIRSTG  (32 * BROWB)       // 4608 bytes: one pair-stage (32 rows x 64 cols)
#define PAIRB    (NSTAGE * PAIRSTG) // 13824 per pair
#define SM_TOTAL (ABYTES + 8 * PAIRB)   // 210944

#define NTHREADS 512
#define TILEBYTES ((size_t)TILE_N * CDIM * 2)   // gmem bytes per bank tile row-block

// ---------------- scratch ----------------
__device__ __align__(16) __nv_bfloat16 g_pat_bf[(size_t)NPATCH * CDIM];
__device__ __align__(16) __nv_bfloat16 g_bank_bf[(size_t)MBANK_PAD * CDIM];
__device__ float g_xsq[NPATCH];
__device__ float g_msq[MBANK_PAD];
__device__ float g_part[MSPLIT * NPATCH];

__device__ __forceinline__ uint32_t s2u(const void* p) {
    uint32_t r;
    asm("{ .reg .u64 t; cvta.to.shared.u64 t, %1; cvt.u32.u64 %0, t; }"
        : "=r"(r) : "l"(p));
    return r;
}

// ============================ prep kernels ============================
// One warp per patch: embed (f2 ++ bilinear-upsampled f3), bf16 round, write
// row + squared norm of the rounded values. Single pass, no re-read.
__global__ void embed_kernel(const float* __restrict__ f2,
                             const float* __restrict__ f3) {
    int n    = (blockIdx.x * blockDim.x + threadIdx.x) >> 5;
    int lane = threadIdx.x & 31;
    if (n >= NPATCH) return;
    int b = n / (HDIM * WDIM);
    int hw = n - b * (HDIM * WDIM);
    int h = hw / WDIM;
    int w = hw - h * WDIM;

    // bilinear coords (shared by all c3 channels)
    float sh = h * 0.5f - 0.25f;
    float sw = w * 0.5f - 0.25f;
    int h0 = (int)floorf(sh);
    int w0 = (int)floorf(sw);
    float th = sh - (float)h0;
    float tw = sw - (float)w0;
    int h0c = h0 < 0 ? 0 : h0;   int h1c = h0 + 1 > H3 - 1 ? H3 - 1 : h0 + 1;
    int w0c = w0 < 0 ? 0 : w0;   int w1c = w0 + 1 > W3 - 1 ? W3 - 1 : w0 + 1;

    __nv_bfloat16* dst = g_pat_bf + (size_t)n * CDIM;
    float sumsq = 0.f;
    #pragma unroll
    for (int j = 0; j < 12; ++j) {
        int c = lane + j * 32;
        float val;
        if (c < C2DIM) {
            val = f2[(((size_t)b * C2DIM + c) * HDIM + h) * WDIM + w];
        } else {
            int c3 = c - C2DIM;
            const float* base = f3 + ((size_t)b * C3DIM + c3) * (H3 * W3);
            float v00 = base[h0c * W3 + w0c];
            float v01 = base[h0c * W3 + w1c];
            float v10 = base[h1c * W3 + w0c];
            float v11 = base[h1c * W3 + w1c];
            val = (1.f - th) * ((1.f - tw) * v00 + tw * v01)
                +        th  * ((1.f - tw) * v10 + tw * v11);
        }
        __nv_bfloat16 bv = __float2bfloat16(val);
        dst[c] = bv;
        float f = __bfloat162float(bv);
        sumsq += f * f;
    }
    #pragma unroll
    for (int off = 16; off; off >>= 1)
        sumsq += __shfl_xor_sync(0xffffffffu, sumsq, off);
    if (lane == 0) g_xsq[n] = sumsq;
}

// bank fp32 -> bf16 (+ zero pad rows) + squared norm of rounded values
__global__ void bankcvt_kernel(const float* __restrict__ bank) {
    int warp = (blockIdx.x * blockDim.x + threadIdx.x) >> 5;
    int lane = threadIdx.x & 31;
    if (warp >= MBANK_PAD) return;
    uint32_t* dst = (uint32_t*)(g_bank_bf + (size_t)warp * CDIM);
    if (warp >= MBANK) {
        #pragma unroll
        for (int j = 0; j < CDIM / 64; ++j) dst[j * 32 + lane] = 0u;
        if (lane == 0) g_msq[warp] = __int_as_float(0x7f800000);
        return;
    }
    const float2* src = (const float2*)(bank + (size_t)warp * CDIM);
    float s = 0.f;
    #pragma unroll
    for (int j = 0; j < CDIM / 64; ++j) {
        float2 v = src[j * 32 + lane];
        __nv_bfloat162 bv = __float22bfloat162_rn(v);
        dst[j * 32 + lane] = *(uint32_t*)&bv;
        float f0 = __bfloat162float(bv.x), f1 = __bfloat162float(bv.y);
        s += f0 * f0 + f1 * f1;
    }
    #pragma unroll
    for (int off = 16; off; off >>= 1) s += __shfl_xor_sync(0xffffffffu, s, off);
    if (lane == 0) g_msq[warp] = s;
}

// ============================ main GEMM+min kernel ============================
// 512 threads, 16 warps in 2(m) x 8(n); warp tile 64x32, mma.m16n8k16 bf16.
// Warp-pair (wm0,wm1 of same wn) shares a private 3-stage B ring; pairs sync
// with named bar.sync. j-loop fully unrolled (6 chunks, stage = j%3).
__global__ void __launch_bounds__(NTHREADS, 1) nn_kernel() {
    extern __shared__ __align__(1024) char smem[];
    char* Asm = smem;
    const int tid  = threadIdx.x;
    const int lane = tid & 31;
    const int wid  = tid >> 5;
    const int wm   = wid >> 3;      // 0..1
    const int wn   = wid & 7;       // 0..7
    const int n0   = blockIdx.x * TILE_M;
    const int split = blockIdx.y;
    const int mbase = split * (BTILES * TILE_N);

    const uint32_t aSm = s2u(smem);
    const uint32_t bSm = aSm + ABYTES + (uint32_t)wn * PAIRB;   // pair region

    // ---- load A tile (128 x 384 bf16) into smem, stride 392 ----
    #pragma unroll
    for (int i = 0; i < 12; ++i) {
        int e = i * NTHREADS + tid;
        int r = e / 48, q = e - r * 48;
        uint4 v = *(const uint4*)(g_pat_bf + (size_t)(n0 + r) * CDIM + q * 8);
        *(uint4*)(Asm + r * (ASTRIDE * 2) + q * 16) = v;
    }

    // per-lane ldmatrix base addresses
    const uint32_t aBase = aSm +
        ((wm * 64 + (lane & 15)) * ASTRIDE + (lane >> 4) * 8) * 2;
    const int lq = lane >> 3;
    const int bn = (lane & 7) + ((lq >> 1) << 3);    // local row 0..15
    const int bk = (lq & 1) << 3;
    const uint32_t bBase = bSm + bn * BROWB + bk * 2;

    float rowmin[4][2];
    #pragma unroll
    for (int i = 0; i < 4; ++i) {
        rowmin[i][0] = __int_as_float(0x7f800000);
        rowmin[i][1] = __int_as_float(0x7f800000);
    }

    // ---- pair chunk loader: 32 rows x 64 k-cols bf16 = 4KB, 2 warps split ----
    const int l64 = wm * 32 + lane;   // 0..63 within the pair
    const int lr = l64 >> 3, lqq = l64 & 7;   // each thread: 4 rows x 1 quad
    auto load_at = [&](const char* src0, uint32_t dbase) {
        #pragma unroll
        for (int i = 0; i < 4; ++i) {
            int r = lr + i * 8;
            uint32_t d = dbase + r * BROWB + lqq * 16;
            const char* s = src0 + (size_t)r * (CDIM * 2) + lqq * 16;
            asm volatile("cp.async.cg.shared.global [%0], [%1], 16;"
                         :: "r"(d), "l"(s));
        }
        asm volatile("cp.async.commit_group;");
    };

    // pair's gmem base for tile 0
    const char* tileSrc = (const char*)(g_bank_bf +
                          (size_t)(mbase + wn * 32) * CDIM);

    load_at(tileSrc + 0 * 128, bSm + 0 * PAIRSTG);   // chunk 0 -> stage 0
    load_at(tileSrc + 1 * 128, bSm + 1 * PAIRSTG);   // chunk 1 -> stage 1
    __syncthreads();   // covers A-tile stores

    const int barid = wn + 1;
    for (int t = 0; t < BTILES; ++t) {
        float acc[4][4][4];
        #pragma unroll
        for (int mt = 0; mt < 4; ++mt)
            #pragma unroll
            for (int nt = 0; nt < 4; ++nt)
                #pragma unroll
                for (int e = 0; e < 4; ++e) acc[mt][nt][e] = 0.f;

        const bool more = (t + 1) < BTILES;
        const char* nextSrc = tileSrc + TILEBYTES;
        float ms[4][2];

        #pragma unroll
        for (int j = 0; j < 6; ++j) {
            asm volatile("cp.async.wait_group 1;");   // own chunk j resident
            asm volatile("bar.sync %0, 64;" :: "r"(barid) : "memory");
            // load chunk j+2 into stage (j+2)%3
            if (j < 4) {
                load_at(tileSrc + (j + 2) * 128,
                        bSm + (uint32_t)(((j + 2) % 3) * PAIRSTG));
            } else if (more) {
                load_at(nextSrc + (j - 4) * 128,
                        bSm + (uint32_t)(((j + 2) % 3) * PAIRSTG));
            } else {
                asm volatile("cp.async.commit_group;");  // keep group count
            }
            if (j == 5) {   // prefetch msq for the fold (hidden by final MMAs)
                const int cb = mbase + t * TILE_N + wn * 32 + (lane & 3) * 2;
                #pragma unroll
                for (int nt = 0; nt < 4; ++nt) {
                    ms[nt][0] = __ldg(&g_msq[cb + nt * 8]);
                    ms[nt][1] = __ldg(&g_msq[cb + nt * 8 + 1]);
                }
            }

            const uint32_t bBuf = bBase + (uint32_t)((j % 3) * PAIRSTG);
            #pragma unroll
            for (int s = 0; s < 4; ++s) {
                // B frags first (feed all 16 MMAs): 2 x4-ldmatrix -> 4 n8-tiles
                uint32_t b[4][2];
                #pragma unroll
                for (int np = 0; np < 2; ++np) {
                    uint32_t r0, r1, r2, r3;
                    uint32_t ad = bBuf + np * (16 * BROWB) + s * 32;
                    asm volatile(
                        "ldmatrix.sync.aligned.m8n8.x4.shared.b16 "
                        "{%0,%1,%2,%3}, [%4];"
                        : "=r"(r0), "=r"(r1), "=r"(r2), "=r"(r3) : "r"(ad));
                    b[2 * np][0] = r0; b[2 * np][1] = r1;
                    b[2 * np + 1][0] = r2; b[2 * np + 1][1] = r3;
                }
                // A frags: 4 x4-ldmatrix -> 4 m16-tiles x {a0..a3}
                uint32_t a[4][4];
                #pragma unroll
                for (int mt = 0; mt < 4; ++mt) {
                    uint32_t ad = aBase + mt * (16 * ASTRIDE * 2)
                                + (j * 64 + s * 16) * 2;
                    asm volatile(
                        "ldmatrix.sync.aligned.m8n8.x4.shared.b16 "
                        "{%0,%1,%2,%3}, [%4];"
                        : "=r"(a[mt][0]), "=r"(a[mt][1]),
                          "=r"(a[mt][2]), "=r"(a[mt][3]) : "r"(ad));
                }
                #pragma unroll
                for (int mt = 0; mt < 4; ++mt)
                    #pragma unroll
                    for (int nt = 0; nt < 4; ++nt) {
                        asm volatile(
                            "mma.sync.aligned.m16n8k16.row.col.f32.bf16.bf16.f32 "
                            "{%0,%1,%2,%3}, {%4,%5,%6,%7}, {%8,%9}, {%0,%1,%2,%3};"
                            : "+f"(acc[mt][nt][0]), "+f"(acc[mt][nt][1]),
                              "+f"(acc[mt][nt][2]), "+f"(acc[mt][nt][3])
                            : "r"(a[mt][0]), "r"(a[mt][1]),
                              "r"(a[mt][2]), "r"(a[mt][3]),
                              "r"(b[nt][0]), "r"(b[nt][1]));
                    }
            }
        }
        tileSrc = nextSrc;

        // ---- fold tile into persistent row-min regs (msq already in regs) ----
        #pragma unroll
        for (int nt = 0; nt < 4; ++nt) {
            float m0 = ms[nt][0];
            float m1 = ms[nt][1];
            #pragma unroll
            for (int mt = 0; mt < 4; ++mt) {
                float v0 = fmaf(-2.f, acc[mt][nt][0], m0);
                float v1 = fmaf(-2.f, acc[mt][nt][1], m1);
                float v2 = fmaf(-2.f, acc[mt][nt][2], m0);
                float v3 = fmaf(-2.f, acc[mt][nt][3], m1);
                rowmin[mt][0] = fminf(rowmin[mt][0], fminf(v0, v1));
                rowmin[mt][1] = fminf(rowmin[mt][1], fminf(v2, v3));
            }
        }
    }

    // ---- final reduction: lanes sharing rows, then across wn warps ----
    #pragma unroll
    for (int mt = 0; mt < 4; ++mt)
        #pragma unroll
        for (int h = 0; h < 2; ++h) {
            float v = rowmin[mt][h];
            v = fminf(v, __shfl_xor_sync(0xffffffffu, v, 1));
            v = fminf(v, __shfl_xor_sync(0xffffffffu, v, 2));
            rowmin[mt][h] = v;
        }
    asm volatile("cp.async.wait_group 0;");
    __syncthreads();
    float* red = (float*)Asm;      // [8 wn][128 rows], aliases A region
    if ((lane & 3) == 0) {
        #pragma unroll
        for (int mt = 0; mt < 4; ++mt)
            #pragma unroll
            for (int h = 0; h < 2; ++h) {
                int row = wm * 64 + mt * 16 + (lane >> 2) + h * 8;
                red[wn * 128 + row] = rowmin[mt][h];
            }
    }
    __syncthreads();
    if (tid < 128) {
        float v = red[tid];
        #pragma unroll
        for (int wq = 1; wq < 8; ++wq)
            v = fminf(v, red[wq * 128 + tid]);
        g_part[split * NPATCH + n0 + tid] = v;
    }
}

// ============================ finalize ============================
__global__ void finalize_kernel(float* __restrict__ out) {
    int n = blockIdx.x * blockDim.x + threadIdx.x;
    if (n >= NPATCH) return;
    float m = fminf(g_part[n], fminf(g_part[NPATCH + n], g_part[2 * NPATCH + n]));
    float d2 = g_xsq[n] + m;
    d2 = fmaxf(d2, 1e-12f);
    out[n] = sqrtf(d2);
}

__global__ void img_max_kernel(float* __restrict__ out) {
    __shared__ float red[8];
    int b = blockIdx.x;
    int tid = threadIdx.x;
    float v = -3.0e38f;
    for (int i = tid; i < HDIM * WDIM; i += blockDim.x)
        v = fmaxf(v, out[b * (HDIM * WDIM) + i]);
    #pragma unroll
    for (int off = 16; off; off >>= 1)
        v = fmaxf(v, __shfl_xor_sync(0xffffffffu, v, off));
    if ((tid & 31) == 0) red[tid >> 5] = v;
    __syncthreads();
    if (tid < 8) {
        v = red[tid];
        #pragma unroll
        for (int off = 4; off; off >>= 1)
            v = fmaxf(v, __shfl_xor_sync(0x000000ffu, v, off));
        if (tid == 0) out[NPATCH + b] = v;
    }
}

// ============================ launch ============================
extern "C" void kernel_launch(void* const* d_in, const int* in_sizes, int n_in,
                              void* d_out, int out_size) {
    const float* f2   = (const float*)d_in[0];
    const float* f3   = (const float*)d_in[1];
    const float* bank = (const float*)d_in[2];
    float* out = (float*)d_out;

    cudaFuncSetAttribute(nn_kernel,
                         cudaFuncAttributeMaxDynamicSharedMemorySize, SM_TOTAL);

    embed_kernel<<<(NPATCH * 32 + 255) / 256, 256>>>(f2, f3);
    bankcvt_kernel<<<(MBANK_PAD * 32 + 255) / 256, 256>>>(bank);

    dim3 grid(NTILES, MSPLIT);
    nn_kernel<<<grid, NTHREADS, SM_TOTAL>>>();

    finalize_kernel<<<(NPATCH + 255) / 256, 256>>>(out);
    if (out_size >= NPATCH + BATCH)
        img_max_kernel<<<BATCH, 256>>>(out);
}